// round 11
// baseline (speedup 1.0000x reference)
#include <cuda_runtime.h>
#include <cuda_fp16.h>

// LightGCN 3-hop propagation on GB300 — round 11.
// Base = R8 (best: 148.2us) + fill4. New: SpMM inner loop accumulates in
// fp16 via HFMA2 (4 ops/edge vs 8 F2F + 8 FFMA), dual short chains (depth
// ~2) per element to bound rounding; promotion to fp32 happens once per row
// before the cross-octet reduction. R10 pipeline reverted (occupancy loss).

#define NUSERS   100000
#define NITEMS   50000
#define NNODES   150000
#define DIM      64
#define NNZ_MAX  2400000
#define CAP      64
#define CAP_SH   6

// ---- scratch (static device globals; no runtime allocation allowed) ----
static __device__ __half2       g_x0h[NNODES * (DIM / 2)];
static __device__ __half2       g_x1h[NNODES * (DIM / 2)];
static __device__ __half2       g_x2h[NNODES * (DIM / 2)];
static __device__ int           g_cnt[NNODES];
static __device__ unsigned char g_need[NNODES];
static __device__ int2          g_csr[(size_t)NNODES * CAP];   // {col, val_bits}

// ---- convert fp32 inputs -> fp16 x0 table ----
__global__ __launch_bounds__(256) void convert_kernel(const float2* __restrict__ ue,
                                                      const float2* __restrict__ ie) {
    int idx = blockIdx.x * blockDim.x + threadIdx.x;   // half2 units (32/row)
    if (idx >= NNODES * 32) return;
    float2 v = (idx < NUSERS * 32) ? ue[idx] : ie[idx - NUSERS * 32];
    g_x0h[idx] = __float22half2_rn(v);
}

// ---- bucket fill, 4 edges per thread ----
__global__ __launch_bounds__(256) void fill4_kernel(const int4* __restrict__ rows4,
                                                    const int4* __restrict__ cols4,
                                                    const float4* __restrict__ vals4,
                                                    int nnz) {
    int t = blockIdx.x * blockDim.x + threadIdx.x;
    int e0 = t * 4;
    if (e0 >= nnz) return;
    if (e0 + 4 <= nnz) {
        int4 r = rows4[t];
        int4 c = cols4[t];
        float4 v = vals4[t];
        int p;
        p = atomicAdd(&g_cnt[r.x], 1); if (p < CAP) g_csr[((size_t)r.x << CAP_SH) + p] = make_int2(c.x, __float_as_int(v.x));
        p = atomicAdd(&g_cnt[r.y], 1); if (p < CAP) g_csr[((size_t)r.y << CAP_SH) + p] = make_int2(c.y, __float_as_int(v.y));
        p = atomicAdd(&g_cnt[r.z], 1); if (p < CAP) g_csr[((size_t)r.z << CAP_SH) + p] = make_int2(c.z, __float_as_int(v.z));
        p = atomicAdd(&g_cnt[r.w], 1); if (p < CAP) g_csr[((size_t)r.w << CAP_SH) + p] = make_int2(c.w, __float_as_int(v.w));
    } else {
        const int*   rows = (const int*)rows4;
        const int*   cols = (const int*)cols4;
        const float* vals = (const float*)vals4;
        for (int e = e0; e < nnz; e++) {
            int r = rows[e];
            int p = atomicAdd(&g_cnt[r], 1);
            if (p < CAP) g_csr[((size_t)r << CAP_SH) + p] = make_int2(cols[e], __float_as_int(vals[e]));
        }
    }
}

// ---- mark rows of x2 that the fused hop3/output stage will read ----
__global__ __launch_bounds__(256) void mask_kernel(const int* __restrict__ uids,
                                                   const int* __restrict__ iids,
                                                   int nu, int ni) {
    int warp = (blockIdx.x * blockDim.x + threadIdx.x) >> 5;
    int lane = threadIdx.x & 31;
    if (warp >= nu + ni) return;
    int node = (warp < nu) ? uids[warp] : (NUSERS + iids[warp - nu]);
    if (lane == 0) g_need[node] = 1;
    int cnt = g_cnt[node];
    if (cnt > CAP) cnt = CAP;
    const int2* __restrict__ row = g_csr + ((size_t)node << CAP_SH);
    for (int e = lane; e < cnt; e += 32)
        g_need[row[e].x] = 1;
}

static __device__ __forceinline__ int4 slice_ld(const __half2* __restrict__ x,
                                                int col, int sub) {
    return *(const int4*)((const char*)x + (((unsigned)col << 7) + ((unsigned)sub << 4)));
}

// accumulate one gathered slice in fp16: h += v * q (4 HFMA2)
static __device__ __forceinline__ void hconsume(__half2 v, int4 q,
                                                __half2& h0, __half2& h1,
                                                __half2& h2, __half2& h3) {
    h0 = __hfma2(*(const __half2*)&q.x, v, h0);
    h1 = __hfma2(*(const __half2*)&q.y, v, h1);
    h2 = __hfma2(*(const __half2*)&q.z, v, h2);
    h3 = __hfma2(*(const __half2*)&q.w, v, h3);
}

// ---- octet SpMM, fp16 HFMA2 accumulation (dual chains), fp32 reduction ----
// y[row] = fp16( sum_e val[e] * x[col[e]] ); use_mask: skip rows not in g_need.
__global__ __launch_bounds__(256) void spmm_h_kernel(const __half2* __restrict__ x,
                                                     __half2* __restrict__ y,
                                                     int use_mask) {
    int warp = (blockIdx.x * blockDim.x + threadIdx.x) >> 5;
    int lane = threadIdx.x & 31;
    if (warp >= NNODES) return;
    if (use_mask && !g_need[warp]) return;
    int oct = lane >> 3;
    int sub = lane & 7;

    const int2* __restrict__ csr_row = g_csr + ((size_t)warp << CAP_SH);
    int cnt = g_cnt[warp];
    if (cnt > CAP) cnt = CAP;

    __half2 z = __float2half2_rn(0.f);
    __half2 a0 = z, a1 = z, a2 = z, a3 = z;   // chain A (edges e+oct)
    __half2 b0 = z, b1 = z, b2 = z, b3 = z;   // chain B (edges e+4+oct)

    int n8 = cnt & ~7;
    for (int e = 0; e < n8; e += 8) {
        int2 ea = csr_row[e + oct];
        int2 eb = csr_row[e + 4 + oct];
        int4 qa = slice_ld(x, ea.x, sub);
        int4 qb = slice_ld(x, eb.x, sub);
        __half2 va = __float2half2_rn(__int_as_float(ea.y));
        __half2 vb = __float2half2_rn(__int_as_float(eb.y));
        hconsume(va, qa, a0, a1, a2, a3);
        hconsume(vb, qb, b0, b1, b2, b3);
    }
    int rem = cnt - n8;
    if (oct < rem) {
        int2 ed = csr_row[n8 + oct];
        int4 q = slice_ld(x, ed.x, sub);
        hconsume(__float2half2_rn(__int_as_float(ed.y)), q, a0, a1, a2, a3);
    }
    if (oct + 4 < rem) {
        int2 ed = csr_row[n8 + 4 + oct];
        int4 q = slice_ld(x, ed.x, sub);
        hconsume(__float2half2_rn(__int_as_float(ed.y)), q, b0, b1, b2, b3);
    }

    // promote dual fp16 chains to fp32 and merge
    float2 s0, s1, s2, s3;
    {
        float2 fa, fb;
        fa = __half22float2(a0); fb = __half22float2(b0); s0 = make_float2(fa.x + fb.x, fa.y + fb.y);
        fa = __half22float2(a1); fb = __half22float2(b1); s1 = make_float2(fa.x + fb.x, fa.y + fb.y);
        fa = __half22float2(a2); fb = __half22float2(b2); s2 = make_float2(fa.x + fb.x, fa.y + fb.y);
        fa = __half22float2(a3); fb = __half22float2(b3); s3 = make_float2(fa.x + fb.x, fa.y + fb.y);
    }

    // cross-octet reduction in fp32 (xor 8, xor 16)
#pragma unroll
    for (int st = 8; st <= 16; st <<= 1) {
        s0.x += __shfl_xor_sync(0xffffffffu, s0.x, st);
        s0.y += __shfl_xor_sync(0xffffffffu, s0.y, st);
        s1.x += __shfl_xor_sync(0xffffffffu, s1.x, st);
        s1.y += __shfl_xor_sync(0xffffffffu, s1.y, st);
        s2.x += __shfl_xor_sync(0xffffffffu, s2.x, st);
        s2.y += __shfl_xor_sync(0xffffffffu, s2.y, st);
        s3.x += __shfl_xor_sync(0xffffffffu, s3.x, st);
        s3.y += __shfl_xor_sync(0xffffffffu, s3.y, st);
    }

    if (oct == 0) {
        __half2 h0 = __float22half2_rn(s0);
        __half2 h1 = __float22half2_rn(s1);
        __half2 h2 = __float22half2_rn(s2);
        __half2 h3 = __float22half2_rn(s3);
        int4 o;
        o.x = *(const int*)&h0; o.y = *(const int*)&h1;
        o.z = *(const int*)&h2; o.w = *(const int*)&h3;
        *(int4*)((char*)y + (((unsigned)warp << 7) + ((unsigned)sub << 4))) = o;
    }
}

// ---- fused hop-3 + accumulate + gather over the 8192 output rows ----
// (fp32 accumulation — tiny kernel, keep max precision)
__global__ __launch_bounds__(256) void hop3_out_kernel(const int* __restrict__ uids,
                                                       const int* __restrict__ iids,
                                                       const float2* __restrict__ ue2,
                                                       const float2* __restrict__ ie2,
                                                       const __half2* __restrict__ x1,
                                                       const __half2* __restrict__ x2,
                                                       float2* __restrict__ out,
                                                       int nu, int ni) {
    int warp = (blockIdx.x * blockDim.x + threadIdx.x) >> 5;
    int lane = threadIdx.x & 31;
    if (warp >= nu + ni) return;

    int node;
    const float2* __restrict__ x0row;
    if (warp < nu) {
        int u = uids[warp];
        node = u;
        x0row = ue2 + (size_t)u * 32;
    } else {
        int it = iids[warp - nu];
        node = NUSERS + it;
        x0row = ie2 + (size_t)it * 32;
    }

    const int4* __restrict__ row4 = (const int4*)(g_csr + ((size_t)node << CAP_SH));
    int cnt = g_cnt[node];
    if (cnt > CAP) cnt = CAP;

    float2 sum = make_float2(0.f, 0.f);
    int e = 0;
    for (; e + 4 <= cnt; e += 4) {
        int4 p0 = row4[(e >> 1)];
        int4 p1 = row4[(e >> 1) + 1];
        float2 xa = __half22float2(x2[(size_t)p0.x * 32 + lane]);
        float2 xb = __half22float2(x2[(size_t)p0.z * 32 + lane]);
        float2 xc = __half22float2(x2[(size_t)p1.x * 32 + lane]);
        float2 xd = __half22float2(x2[(size_t)p1.z * 32 + lane]);
        float va = __int_as_float(p0.y), vb = __int_as_float(p0.w);
        float vc = __int_as_float(p1.y), vd = __int_as_float(p1.w);
        sum.x += va * xa.x; sum.y += va * xa.y;
        sum.x += vb * xb.x; sum.y += vb * xb.y;
        sum.x += vc * xc.x; sum.y += vc * xc.y;
        sum.x += vd * xd.x; sum.y += vd * xd.y;
    }
    const int2* __restrict__ row = g_csr + ((size_t)node << CAP_SH);
    for (; e < cnt; e++) {
        int2 ed = row[e];
        float v = __int_as_float(ed.y);
        float2 xv = __half22float2(x2[(size_t)ed.x * 32 + lane]);
        sum.x += v * xv.x;
        sum.y += v * xv.y;
    }

    float2 r0 = x0row[lane];
    float2 r1 = __half22float2(x1[(size_t)node * 32 + lane]);
    float2 r2 = __half22float2(x2[(size_t)node * 32 + lane]);
    float2 o;
    o.x = 0.25f * (r0.x + r1.x + r2.x + sum.x);
    o.y = 0.25f * (r0.y + r1.y + r2.y + sum.y);
    out[(size_t)warp * 32 + lane] = o;
}

extern "C" void kernel_launch(void* const* d_in, const int* in_sizes, int n_in,
                              void* d_out, int out_size) {
    const float* user_emb  = (const float*)d_in[0];
    const float* item_emb  = (const float*)d_in[1];
    const float* edge_vals = (const float*)d_in[2];
    const int*   edge_rows = (const int*)d_in[3];
    const int*   edge_cols = (const int*)d_in[4];
    const int*   user_ids  = (const int*)d_in[5];
    const int*   item_ids  = (const int*)d_in[6];
    float*       out       = (float*)d_out;

    int nnz = in_sizes[2];
    if (nnz > NNZ_MAX) nnz = NNZ_MAX;
    int nu = in_sizes[5];
    int ni = in_sizes[6];

    __half2 *x0h, *x1h, *x2h;
    int *cnt;
    unsigned char *need;
    cudaGetSymbolAddress((void**)&x0h, g_x0h);
    cudaGetSymbolAddress((void**)&x1h, g_x1h);
    cudaGetSymbolAddress((void**)&x2h, g_x2h);
    cudaGetSymbolAddress((void**)&cnt, g_cnt);
    cudaGetSymbolAddress((void**)&need, g_need);

    // bucket-CSR build
    cudaMemsetAsync(cnt, 0, NNODES * sizeof(int));
    cudaMemsetAsync(need, 0, NNODES);
    {
        int n = NNODES * 32;
        convert_kernel<<<(n + 255) / 256, 256>>>((const float2*)user_emb,
                                                 (const float2*)item_emb);
    }
    {
        int nt = (nnz + 3) / 4;
        fill4_kernel<<<(nt + 255) / 256, 256>>>((const int4*)edge_rows,
                                                (const int4*)edge_cols,
                                                (const float4*)edge_vals, nnz);
    }

    // mark x2 rows that hop3/output will read
    int nout_warps = nu + ni;
    mask_kernel<<<(nout_warps + 7) / 8, 256>>>(user_ids, item_ids, nu, ni);

    // hops 1 (full) and 2 (masked)
    int spmm_blocks = (NNODES + 7) / 8;
    spmm_h_kernel<<<spmm_blocks, 256>>>(x0h, x1h, 0);
    spmm_h_kernel<<<spmm_blocks, 256>>>(x1h, x2h, 1);

    // hop 3 + accumulate + gather, only over the requested 8192 rows
    hop3_out_kernel<<<(nout_warps + 7) / 8, 256>>>(user_ids, item_ids,
                                                   (const float2*)user_emb,
                                                   (const float2*)item_emb,
                                                   x1h, x2h,
                                                   (float2*)out, nu, ni);
}

// round 12
// speedup vs baseline: 1.1620x; 1.1620x over previous
#include <cuda_runtime.h>
#include <cuda_fp16.h>

// LightGCN 3-hop propagation on GB300 — round 12.
// Kernels are byte-identical to R8's (best measured SpMM: 32 regs, 79% occ).
// Change: block-split fusion of independent stages to remove serial time —
//   K1 = fill ∥ convert   (independent outputs; atomic/L2-heavy ∥ DRAM-heavy)
//   K2 = hop1 ∥ mask      (mask's g_need only read by hop2)
// fill4 / ffma2 / pipeline / hfma2 all reverted (measured regressions).

#define NUSERS   100000
#define NITEMS   50000
#define NNODES   150000
#define DIM      64
#define NNZ_MAX  2400000
#define CAP      64
#define CAP_SH   6

// ---- scratch (static device globals; no runtime allocation allowed) ----
static __device__ __half2       g_x0h[NNODES * (DIM / 2)];
static __device__ __half2       g_x1h[NNODES * (DIM / 2)];
static __device__ __half2       g_x2h[NNODES * (DIM / 2)];
static __device__ int           g_cnt[NNODES];
static __device__ unsigned char g_need[NNODES];
static __device__ int2          g_csr[(size_t)NNODES * CAP];   // {col, val_bits}

// ================= device bodies =================

static __device__ __forceinline__ void convert_body(int idx,
                                                    const float2* __restrict__ ue,
                                                    const float2* __restrict__ ie) {
    if (idx >= NNODES * 32) return;
    float2 v = (idx < NUSERS * 32) ? ue[idx] : ie[idx - NUSERS * 32];
    g_x0h[idx] = __float22half2_rn(v);
}

static __device__ __forceinline__ void fill_body(int e,
                                                 const int* __restrict__ rows,
                                                 const int* __restrict__ cols,
                                                 const float* __restrict__ vals,
                                                 int nnz) {
    if (e >= nnz) return;
    int r = rows[e];
    int pos = atomicAdd(&g_cnt[r], 1);
    if (pos < CAP)
        g_csr[((size_t)r << CAP_SH) + pos] = make_int2(cols[e], __float_as_int(vals[e]));
}

static __device__ __forceinline__ void mask_body(int warp, int lane,
                                                 const int* __restrict__ uids,
                                                 const int* __restrict__ iids,
                                                 int nu, int ni) {
    if (warp >= nu + ni) return;
    int node = (warp < nu) ? uids[warp] : (NUSERS + iids[warp - nu]);
    if (lane == 0) g_need[node] = 1;
    int cnt = g_cnt[node];
    if (cnt > CAP) cnt = CAP;
    const int2* __restrict__ row = g_csr + ((size_t)node << CAP_SH);
    for (int e = lane; e < cnt; e += 32)
        g_need[row[e].x] = 1;
}

// one edge, one lane's 16-byte fp16 slice (identical to R8)
static __device__ __forceinline__ void edge_body(const __half2* __restrict__ x,
                                                 const int2* __restrict__ csr_row,
                                                 int idx, int sub,
                                                 float2& s0, float2& s1,
                                                 float2& s2, float2& s3) {
    int2 ed = csr_row[idx];
    float v = __int_as_float(ed.y);
    unsigned boff = ((unsigned)ed.x << 7) + ((unsigned)sub << 4);
    int4 q = *(const int4*)((const char*)x + boff);
    float2 f;
    f = __half22float2(*(const __half2*)&q.x); s0.x += v * f.x; s0.y += v * f.y;
    f = __half22float2(*(const __half2*)&q.y); s1.x += v * f.x; s1.y += v * f.y;
    f = __half22float2(*(const __half2*)&q.z); s2.x += v * f.x; s2.y += v * f.y;
    f = __half22float2(*(const __half2*)&q.w); s3.x += v * f.x; s3.y += v * f.y;
}

// octet SpMM row body (identical to R8's spmm_h_kernel body)
static __device__ __forceinline__ void spmm_row_body(int warp, int lane,
                                                     const __half2* __restrict__ x,
                                                     __half2* __restrict__ y,
                                                     int use_mask) {
    if (warp >= NNODES) return;
    if (use_mask && !g_need[warp]) return;
    int oct = lane >> 3;
    int sub = lane & 7;

    const int2* __restrict__ csr_row = g_csr + ((size_t)warp << CAP_SH);
    int cnt = g_cnt[warp];
    if (cnt > CAP) cnt = CAP;

    float2 s0 = make_float2(0.f, 0.f), s1 = s0, s2 = s0, s3 = s0;

    int e = 0;
    int n8 = cnt & ~7;
    for (; e < n8; e += 8) {
        edge_body(x, csr_row, e + oct,     sub, s0, s1, s2, s3);
        edge_body(x, csr_row, e + 4 + oct, sub, s0, s1, s2, s3);
    }
    int rem = cnt - e;
    if (oct < rem)     edge_body(x, csr_row, e + oct,     sub, s0, s1, s2, s3);
    if (oct + 4 < rem) edge_body(x, csr_row, e + 4 + oct, sub, s0, s1, s2, s3);

#pragma unroll
    for (int st = 8; st <= 16; st <<= 1) {
        s0.x += __shfl_xor_sync(0xffffffffu, s0.x, st);
        s0.y += __shfl_xor_sync(0xffffffffu, s0.y, st);
        s1.x += __shfl_xor_sync(0xffffffffu, s1.x, st);
        s1.y += __shfl_xor_sync(0xffffffffu, s1.y, st);
        s2.x += __shfl_xor_sync(0xffffffffu, s2.x, st);
        s2.y += __shfl_xor_sync(0xffffffffu, s2.y, st);
        s3.x += __shfl_xor_sync(0xffffffffu, s3.x, st);
        s3.y += __shfl_xor_sync(0xffffffffu, s3.y, st);
    }

    if (oct == 0) {
        __half2 h0 = __float22half2_rn(s0);
        __half2 h1 = __float22half2_rn(s1);
        __half2 h2 = __float22half2_rn(s2);
        __half2 h3 = __float22half2_rn(s3);
        int4 o;
        o.x = *(const int*)&h0; o.y = *(const int*)&h1;
        o.z = *(const int*)&h2; o.w = *(const int*)&h3;
        *(int4*)((char*)y + (((unsigned)warp << 7) + ((unsigned)sub << 4))) = o;
    }
}

// ================= kernels =================

// K1: blocks [0, nb_fill) do fill; rest do convert.
__global__ __launch_bounds__(256) void k_build(const int* __restrict__ rows,
                                               const int* __restrict__ cols,
                                               const float* __restrict__ vals,
                                               const float2* __restrict__ ue,
                                               const float2* __restrict__ ie,
                                               int nnz, int nb_fill) {
    if ((int)blockIdx.x < nb_fill) {
        fill_body(blockIdx.x * 256 + threadIdx.x, rows, cols, vals, nnz);
    } else {
        convert_body((blockIdx.x - nb_fill) * 256 + threadIdx.x, ue, ie);
    }
}

// K2: blocks [0, nb_spmm) do hop-1 SpMM (unmasked); rest do mask.
__global__ __launch_bounds__(256) void k_hop1_mask(const __half2* __restrict__ x0,
                                                   __half2* __restrict__ x1,
                                                   const int* __restrict__ uids,
                                                   const int* __restrict__ iids,
                                                   int nu, int ni, int nb_spmm) {
    int lane = threadIdx.x & 31;
    if ((int)blockIdx.x < nb_spmm) {
        int warp = (blockIdx.x * 256 + threadIdx.x) >> 5;
        spmm_row_body(warp, lane, x0, x1, 0);
    } else {
        int warp = ((blockIdx.x - nb_spmm) * 256 + threadIdx.x) >> 5;
        mask_body(warp, lane, uids, iids, nu, ni);
    }
}

// hop 2: masked octet SpMM (standalone, identical to R8)
__global__ __launch_bounds__(256) void k_hop2(const __half2* __restrict__ x1,
                                              __half2* __restrict__ x2) {
    int warp = (blockIdx.x * blockDim.x + threadIdx.x) >> 5;
    int lane = threadIdx.x & 31;
    spmm_row_body(warp, lane, x1, x2, 1);
}

// fused hop-3 + accumulate + gather over the 8192 output rows (identical to R8)
__global__ __launch_bounds__(256) void hop3_out_kernel(const int* __restrict__ uids,
                                                       const int* __restrict__ iids,
                                                       const float2* __restrict__ ue2,
                                                       const float2* __restrict__ ie2,
                                                       const __half2* __restrict__ x1,
                                                       const __half2* __restrict__ x2,
                                                       float2* __restrict__ out,
                                                       int nu, int ni) {
    int warp = (blockIdx.x * blockDim.x + threadIdx.x) >> 5;
    int lane = threadIdx.x & 31;
    if (warp >= nu + ni) return;

    int node;
    const float2* __restrict__ x0row;
    if (warp < nu) {
        int u = uids[warp];
        node = u;
        x0row = ue2 + (size_t)u * 32;
    } else {
        int it = iids[warp - nu];
        node = NUSERS + it;
        x0row = ie2 + (size_t)it * 32;
    }

    const int4* __restrict__ row4 = (const int4*)(g_csr + ((size_t)node << CAP_SH));
    int cnt = g_cnt[node];
    if (cnt > CAP) cnt = CAP;

    float2 sum = make_float2(0.f, 0.f);
    int e = 0;
    for (; e + 4 <= cnt; e += 4) {
        int4 p0 = row4[(e >> 1)];
        int4 p1 = row4[(e >> 1) + 1];
        float2 xa = __half22float2(x2[(size_t)p0.x * 32 + lane]);
        float2 xb = __half22float2(x2[(size_t)p0.z * 32 + lane]);
        float2 xc = __half22float2(x2[(size_t)p1.x * 32 + lane]);
        float2 xd = __half22float2(x2[(size_t)p1.z * 32 + lane]);
        float va = __int_as_float(p0.y), vb = __int_as_float(p0.w);
        float vc = __int_as_float(p1.y), vd = __int_as_float(p1.w);
        sum.x += va * xa.x; sum.y += va * xa.y;
        sum.x += vb * xb.x; sum.y += vb * xb.y;
        sum.x += vc * xc.x; sum.y += vc * xc.y;
        sum.x += vd * xd.x; sum.y += vd * xd.y;
    }
    const int2* __restrict__ row = g_csr + ((size_t)node << CAP_SH);
    for (; e < cnt; e++) {
        int2 ed = row[e];
        float v = __int_as_float(ed.y);
        float2 xv = __half22float2(x2[(size_t)ed.x * 32 + lane]);
        sum.x += v * xv.x;
        sum.y += v * xv.y;
    }

    float2 r0 = x0row[lane];
    float2 r1 = __half22float2(x1[(size_t)node * 32 + lane]);
    float2 r2 = __half22float2(x2[(size_t)node * 32 + lane]);
    float2 o;
    o.x = 0.25f * (r0.x + r1.x + r2.x + sum.x);
    o.y = 0.25f * (r0.y + r1.y + r2.y + sum.y);
    out[(size_t)warp * 32 + lane] = o;
}

extern "C" void kernel_launch(void* const* d_in, const int* in_sizes, int n_in,
                              void* d_out, int out_size) {
    const float* user_emb  = (const float*)d_in[0];
    const float* item_emb  = (const float*)d_in[1];
    const float* edge_vals = (const float*)d_in[2];
    const int*   edge_rows = (const int*)d_in[3];
    const int*   edge_cols = (const int*)d_in[4];
    const int*   user_ids  = (const int*)d_in[5];
    const int*   item_ids  = (const int*)d_in[6];
    float*       out       = (float*)d_out;

    int nnz = in_sizes[2];
    if (nnz > NNZ_MAX) nnz = NNZ_MAX;
    int nu = in_sizes[5];
    int ni = in_sizes[6];

    __half2 *x0h, *x1h, *x2h;
    int *cnt;
    unsigned char *need;
    cudaGetSymbolAddress((void**)&x0h, g_x0h);
    cudaGetSymbolAddress((void**)&x1h, g_x1h);
    cudaGetSymbolAddress((void**)&x2h, g_x2h);
    cudaGetSymbolAddress((void**)&cnt, g_cnt);
    cudaGetSymbolAddress((void**)&need, g_need);

    cudaMemsetAsync(cnt, 0, NNODES * sizeof(int));
    cudaMemsetAsync(need, 0, NNODES);

    // K1: fill (first, longer) ∥ convert
    int nb_fill = (nnz + 255) / 256;
    int nb_conv = (NNODES * 32 + 255) / 256;
    k_build<<<nb_fill + nb_conv, 256>>>(edge_rows, edge_cols, edge_vals,
                                        (const float2*)user_emb,
                                        (const float2*)item_emb,
                                        nnz, nb_fill);

    // K2: hop-1 SpMM (first, longer) ∥ mask
    int nb_spmm = (NNODES + 7) / 8;
    int nout_warps = nu + ni;
    int nb_mask = (nout_warps + 7) / 8;
    k_hop1_mask<<<nb_spmm + nb_mask, 256>>>(x0h, x1h, user_ids, item_ids,
                                            nu, ni, nb_spmm);

    // hop 2 (masked)
    k_hop2<<<nb_spmm, 256>>>(x1h, x2h);

    // hop 3 + accumulate + gather
    hop3_out_kernel<<<(nout_warps + 7) / 8, 256>>>(user_ids, item_ids,
                                                   (const float2*)user_emb,
                                                   (const float2*)item_emb,
                                                   x1h, x2h,
                                                   (float2*)out, nu, ni);
}